// round 4
// baseline (speedup 1.0000x reference)
#include <cuda_runtime.h>
#include <math.h>

// MTPhysicsLoss: 1D magnetotelluric forward + misfit loss.
// inputs: rho(256), thickness(255), freq(16384), obs_rhoa(16384), obs_phase(16384)
// output: [total_loss, loss_rhoa, loss_phase] (float32)
//
// Impedance recursion as a PROJECTIVE (homogeneous) linear recursion:
//   Z' = (A*Z + B)/(C*Z + D)  with  Z = P/Q  ->  P' = A*P + B*Q ; Q' = C*P + D*Q
//   E  = e^{-x}(cos x - i sin x),  x = s*sqrt(2)*t/sqrt(rho),  s = sqrt(omega*mu)
//   Zj = a(1+i), a = s*sqrt(rho/2)
//   A = D = Zj(1-E),  B = Zj^2(1+E) = 2a^2 i (1+E),  C = (1+E)
// No division on the critical path; exact power-of-2 renorm every 5 layers.

#define NZ   256
#define NF   16384
#define BLK  128
#define NBLK (NF / BLK)   // 128 blocks, 1 freq per thread, 4 warps/block

#define MU_F        1.2566370614359173e-6f
#define TWO_PI_F    6.283185307179586f
#define INV_SQRT2_F 0.7071067811865476f
#define SQRT2_F     1.4142135623730951f
#define RAD2DEG_F   57.29577951308232f

__device__ float g_part_rhoa[NBLK];
__device__ float g_part_phase[NBLK];

__device__ __forceinline__ float fast_rcp(float x) {
    float r;
    asm("rcp.approx.f32 %0, %1;" : "=f"(r) : "f"(x));
    return r;
}

__global__ __launch_bounds__(BLK, 1)
void mt_forward_kernel(const float* __restrict__ rho,
                       const float* __restrict__ thick,
                       const float* __restrict__ freq,
                       const float* __restrict__ obs_rhoa,
                       const float* __restrict__ obs_phase) {
    __shared__ float sh_h[NZ];       // sqrt(rho_j)/sqrt(2)     -> a = s*h
    __shared__ float sh_g[NZ - 1];   // sqrt(2)*t_j/sqrt(rho_j) -> x = s*g

    const int tid = threadIdx.x;

    #pragma unroll
    for (int j = tid; j < NZ; j += BLK) {
        float sr = sqrtf(rho[j]);
        sh_h[j] = sr * INV_SQRT2_F;
        if (j < NZ - 1) sh_g[j] = SQRT2_F * thick[j] * fast_rcp(sr);
    }
    __syncthreads();

    const int fi = blockIdx.x * BLK + tid;
    const float omu = TWO_PI_F * freq[fi] * MU_F;   // omega*mu
    const float s   = sqrtf(omu);

    // Z0 = a0*(1+i), homogeneous: P = Z0, Q = 1
    const float a0 = s * sh_h[NZ - 1];
    float Pr = a0, Pi = a0;
    float Qr = 1.0f, Qi = 0.0f;

    // 255 layer steps, grouped 51 x 5 with one exact renorm per group.
    for (int base = NZ - 2; base >= 4; base -= 5) {
        #pragma unroll
        for (int k = 0; k < 5; ++k) {
            const int j = base - k;
            const float h = sh_h[j];
            const float g = sh_g[j];
            float a = s * h;
            float x = s * g;
            float e = __expf(-x);
            float sx, cx;
            __sincosf(x, &sx, &cx);
            float ecx = e * cx;         // Re(E)
            float esx = e * sx;         // -Im(E)
            float vr = 1.0f + ecx;      // C = 1+E
            float vi = -esx;
            float w  = 1.0f - ecx;      // Re(1-E); Im(1-E) = esx
            float Ar = a * (w - esx);   // A = Zj(1-E)
            float Ai = a * (w + esx);
            float a2 = a * a;
            float a22 = a2 + a2;        // |Zj^2| factor: Zj^2 = 2a^2 i
            float Br = a22 * esx;       // B = 2a^2 i (1+E)
            float Bi = a22 * vr;

            // P' = A*P + B*Q ; Q' = C*P + A*Q   (complex)
            float Pr_ = fmaf(Ar, Pr, fmaf(-Ai, Pi, fmaf(Br, Qr, -Bi * Qi)));
            float Pi_ = fmaf(Ar, Pi, fmaf( Ai, Pr, fmaf(Br, Qi,  Bi * Qr)));
            float Qr_ = fmaf(vr, Pr, fmaf(-vi, Pi, fmaf(Ar, Qr, -Ai * Qi)));
            float Qi_ = fmaf(vr, Pi, fmaf( vi, Pr, fmaf(Ar, Qi,  Ai * Qr)));
            Pr = Pr_; Pi = Pi_; Qr = Qr_; Qi = Qi_;
        }
        // Exact power-of-two renorm (no rounding error): scale = 2^{-exponent(|Qr|+|Qi|)}
        float m = fabsf(Qr) + fabsf(Qi);
        int ebits = __float_as_int(m) & 0x7F800000;
        float scale = __int_as_float(0x7F000000 - ebits);
        Pr *= scale; Pi *= scale; Qr *= scale; Qi *= scale;
    }

    // Misfits. Z = P/Q: phase from P*conj(Q); log10(|Z|^2) = log10|P|^2 - log10|Q|^2.
    float p2 = fmaf(Pr, Pr, Pi * Pi);
    float q2 = fmaf(Qr, Qr, Qi * Qi);
    float nr = fmaf(Pr, Qr,  Pi * Qi);   // Re(P conj(Q))
    float ni = fmaf(Pi, Qr, -Pr * Qi);   // Im(P conj(Q))
    float dlr = (log10f(p2) - log10f(q2)) - log10f(omu) - log10f(obs_rhoa[fi]);
    float ph  = atan2f(ni, nr) * RAD2DEG_F;
    float dp  = ph - obs_phase[fi];
    float er = dlr * dlr;
    float ep = dp * dp;

    // Deterministic block reduction (4 warps)
    #pragma unroll
    for (int o = 16; o > 0; o >>= 1) {
        er += __shfl_down_sync(0xFFFFFFFFu, er, o);
        ep += __shfl_down_sync(0xFFFFFFFFu, ep, o);
    }
    __shared__ float red[8];
    int lane = tid & 31, warp = tid >> 5;
    if (lane == 0) { red[warp * 2] = er; red[warp * 2 + 1] = ep; }
    __syncthreads();
    if (tid == 0) {
        g_part_rhoa[blockIdx.x]  = (red[0] + red[2]) + (red[4] + red[6]);
        g_part_phase[blockIdx.x] = (red[1] + red[3]) + (red[5] + red[7]);
    }
}

__global__ __launch_bounds__(NBLK, 1)
void mt_reduce_kernel(float* __restrict__ out) {
    const int tid = threadIdx.x;   // 128 threads, 4 warps
    float er = g_part_rhoa[tid];
    float ep = g_part_phase[tid];
    #pragma unroll
    for (int o = 16; o > 0; o >>= 1) {
        er += __shfl_down_sync(0xFFFFFFFFu, er, o);
        ep += __shfl_down_sync(0xFFFFFFFFu, ep, o);
    }
    __shared__ float red[8];
    int lane = tid & 31, warp = tid >> 5;
    if (lane == 0) { red[warp * 2] = er; red[warp * 2 + 1] = ep; }
    __syncthreads();
    if (tid == 0) {
        float sr = (red[0] + red[2]) + (red[4] + red[6]);
        float sp = (red[1] + red[3]) + (red[5] + red[7]);
        float lr = sr * (1.0f / (float)NF);
        float lp = sp * (1.0f / (float)NF);
        out[0] = lr + 10.0f * lp;   // LAMBDA_RHOA=1, LAMBDA_PHASE=10
        out[1] = lr;
        out[2] = lp;
    }
}

extern "C" void kernel_launch(void* const* d_in, const int* in_sizes, int n_in,
                              void* d_out, int out_size) {
    const float* rho       = (const float*)d_in[0];
    const float* thick     = (const float*)d_in[1];
    const float* freq      = (const float*)d_in[2];
    const float* obs_rhoa  = (const float*)d_in[3];
    const float* obs_phase = (const float*)d_in[4];
    float* out = (float*)d_out;

    mt_forward_kernel<<<NBLK, BLK>>>(rho, thick, freq, obs_rhoa, obs_phase);
    mt_reduce_kernel<<<1, NBLK>>>(out);
}